// round 7
// baseline (speedup 1.0000x reference)
#include <cuda_runtime.h>
#include <math.h>
#include <stdint.h>

#define BB    2048
#define DD    256
#define HH    512
#define NSLOT 64
#define FEAT  513
#define FEATP 544
#define G4    2048

#define OFF_H      ((size_t)0)
#define OFF_C      ((size_t)1048576)
#define OFF_HMEM   ((size_t)2097152)
#define OFF_SLOTS  ((size_t)3145728)
#define OFF_CUM    ((size_t)36700160)
#define OFF_DELTA  ((size_t)70254592)
#define OFF_FILLED ((size_t)70385664)

// ------------------------------- scratch ------------------------------------
__device__ float g_q[BB * HH];        // tf32-truncated q
__device__ float g_kq[BB * DD];
__device__ float g_v[BB * DD];
__device__ int   g_idx[BB];
__device__ float g_bias[G4];          // permuted bih+bhh (fp32)
__device__ float g_biaso[G4];         // permuted outer b_ih (fp32)
__device__ float g_wihp[(size_t)G4 * FEATP];   // permuted+padded+trunc lstm_Wih
__device__ float g_whhp[(size_t)G4 * HH];      // permuted+trunc lstm_Whh
__device__ float g_wihop[(size_t)G4 * 768];    // permuted+trunc W_ih
__device__ float g_whhop[(size_t)G4 * HH];     // permuted+trunc W_hh
__device__ float g_xtf[BB * DD];               // trunc x
__device__ float g_hltf[BB * HH];              // trunc h_lstm
__device__ float g_wqtf[HH * DD];
__device__ float g_wkT[DD * HH];               // trunc transpose of Wk
__device__ float g_wvtf[DD * DD];
__device__ float g_mem[(size_t)NSLOT * BB * FEATP];  // trunc mem_seq [n][b][f]
__device__ float g_xg[(size_t)NSLOT * BB * G4];      // permuted xg [n][b][pcol]
__device__ float g_htf0[BB * HH];              // trunc h ping
__device__ float g_htf1[BB * HH];              // trunc h pong
__device__ float g_c[BB * HH];                 // slot-LSTM cell (fp32)
__device__ int   g_fmode;

__device__ __forceinline__ uint32_t f2tf(float x) {
    uint32_t r;
    asm("cvt.rna.tf32.f32 %0, %1;" : "=r"(r) : "f"(x));
    return r;
}
__device__ __forceinline__ float tff(float x) { return __uint_as_float(f2tf(x)); }

__device__ __forceinline__ float sigf(float x) { return 1.0f / (1.0f + __expf(-x)); }
__device__ __forceinline__ float tanh_fast(float x) {
    float t = __expf(-2.0f * fabsf(x));
    float r = (1.0f - t) / (1.0f + t);
    return copysignf(r, x);
}

__device__ __forceinline__ int read_filled(const void* p, size_t i, int m) {
    if (m == 0) return ((const float*)p)[i] != 0.0f;
    if (m == 1) return ((const int*)p)[i] != 0;
    if (m == 2) return ((const unsigned char*)p)[i] != 0;
    return ((const unsigned short*)p)[i] != 0;
}

// ----------------------------- PTX helpers ----------------------------------
__device__ __forceinline__ uint32_t smem_u32(const void* p) {
    uint32_t a;
    asm("{ .reg .u64 t; cvta.to.shared.u64 t, %1; cvt.u32.u64 %0, t; }" : "=r"(a) : "l"(p));
    return a;
}
__device__ __forceinline__ void cpasync16(uint32_t dst, const void* src) {
    asm volatile("cp.async.cg.shared.global [%0], [%1], 16;\n" :: "r"(dst), "l"(src));
}
#define CP_COMMIT() asm volatile("cp.async.commit_group;\n" ::: "memory")
#define CP_WAIT1()  asm volatile("cp.async.wait_group 1;\n" ::: "memory")
#define CP_WAIT0()  asm volatile("cp.async.wait_group 0;\n" ::: "memory")

__device__ __forceinline__ void mma8(float* c, const uint32_t* A, const uint32_t* B) {
    asm volatile(
        "mma.sync.aligned.m16n8k8.row.col.f32.tf32.tf32.f32 "
        "{%0,%1,%2,%3}, {%4,%5,%6,%7}, {%8,%9}, {%0,%1,%2,%3};"
        : "+f"(c[0]), "+f"(c[1]), "+f"(c[2]), "+f"(c[3])
        : "r"(A[0]), "r"(A[1]), "r"(A[2]), "r"(A[3]), "r"(B[0]), "r"(B[1]));
}

// ------------------------- tf32 warp-MMA GEMM -------------------------------
// All GEMM inputs are PRE-TRUNCATED to tf32. C = A[M,K] @ W[N,K]^T (+bias)(+Cin).
// mode 0: plain store (optional tf32-truncated store)
// mode 1: fused slot-LSTM step epilogue (gates permuted 4j+t)
// mode 2: segmented-K outer LSTM (K=1280) + fused epilogue
#define PADK 36
#define TILE_FLOATS 4608                 // 128 * PADK
#define BUF_FLOATS  9216
#define SMEM_DYN    (2 * BUF_FLOATS * 4) // 73728 B; gates tile 128*132*4=67584 fits

struct GArgs {
    int mode, K, lda, ldw, ldc, trunc_out;
    const float *A, *A2, *A3, *W, *W2, *bias, *Cin, *c_in;
    float *C, *c_out, *h_full, *h_tf;
};

__device__ __forceinline__ void load_stage(uint32_t smb, const GArgs& a,
                                           int bm, int bn, int k0, int tid, int buf) {
    const uint32_t base = smb + (uint32_t)buf * BUF_FLOATS * 4;
    const float* Asrc; int lda, ka;
    if (a.mode == 2) {
        if (k0 < 256)      { Asrc = a.A;  lda = 256; ka = k0; }
        else if (k0 < 768) { Asrc = a.A2; lda = 512; ka = k0 - 256; }
        else               { Asrc = a.A3; lda = 512; ka = k0 - 768; }
    } else { Asrc = a.A; lda = a.lda; ka = k0; }
    const float* Wsrc; int ldw, kw;
    if (a.mode == 2) {
        if (k0 < 768) { Wsrc = a.W;  ldw = 768; kw = k0; }
        else          { Wsrc = a.W2; ldw = 512; kw = k0 - 768; }
    } else { Wsrc = a.W; ldw = a.ldw; kw = k0; }
#pragma unroll
    for (int i = 0; i < 4; i++) {
        int idx = tid + i * 256;
        int r = idx >> 3, c = idx & 7;
        cpasync16(base + (uint32_t)(r * PADK + c * 4) * 4,
                  Asrc + (size_t)(bm + r) * lda + ka + c * 4);
    }
#pragma unroll
    for (int i = 0; i < 4; i++) {
        int idx = tid + i * 256;
        int r = idx >> 3, c = idx & 7;
        cpasync16(base + TILE_FLOATS * 4 + (uint32_t)(r * PADK + c * 4) * 4,
                  Wsrc + (size_t)(bn + r) * ldw + kw + c * 4);
    }
}

__global__ void __launch_bounds__(256) mma_gemm_kernel(const GArgs a) {
    extern __shared__ float sm[];
    const uint32_t smb = smem_u32(sm);

    const int tid = threadIdx.x;
    const int wid = tid >> 5, lane = tid & 31;
    const int wm = wid & 3, wn = wid >> 2;
    const int gid = lane >> 2, tg = lane & 3;
    const int bm = blockIdx.y * 128;
    const int bn = blockIdx.x * 128;

    float acc[2][8][4];
#pragma unroll
    for (int mt = 0; mt < 2; mt++)
#pragma unroll
        for (int nt = 0; nt < 8; nt++)
#pragma unroll
            for (int e = 0; e < 4; e++) acc[mt][nt][e] = 0.0f;

    const int KT = a.K >> 5;
    load_stage(smb, a, bm, bn, 0, tid, 0);
    CP_COMMIT();

    for (int kt = 0; kt < KT; kt++) {
        const int cur = kt & 1;
        if (kt + 1 < KT) {
            load_stage(smb, a, bm, bn, (kt + 1) * 32, tid, cur ^ 1);
            CP_COMMIT();
            CP_WAIT1();
        } else {
            CP_WAIT0();
        }
        __syncthreads();

        const float* As = sm + cur * BUF_FLOATS;
        const float* Bs = As + TILE_FLOATS;
#pragma unroll
        for (int k8 = 0; k8 < 4; k8++) {
            const int kb = k8 * 8;
            uint32_t af[2][4];
#pragma unroll
            for (int mt = 0; mt < 2; mt++) {
                int r0 = wm * 32 + mt * 16 + gid;
                af[mt][0] = __float_as_uint(As[r0 * PADK + kb + tg]);
                af[mt][1] = __float_as_uint(As[(r0 + 8) * PADK + kb + tg]);
                af[mt][2] = __float_as_uint(As[r0 * PADK + kb + tg + 4]);
                af[mt][3] = __float_as_uint(As[(r0 + 8) * PADK + kb + tg + 4]);
            }
            uint32_t bf[8][2];
#pragma unroll
            for (int nt = 0; nt < 8; nt++) {
                int n0 = wn * 64 + nt * 8 + gid;
                bf[nt][0] = __float_as_uint(Bs[n0 * PADK + kb + tg]);
                bf[nt][1] = __float_as_uint(Bs[n0 * PADK + kb + tg + 4]);
            }
#pragma unroll
            for (int mt = 0; mt < 2; mt++)
#pragma unroll
                for (int nt = 0; nt < 8; nt++)
                    mma8(acc[mt][nt], af[mt], bf[nt]);
        }
        __syncthreads();
    }

    if (a.mode == 0) {
#pragma unroll
        for (int mt = 0; mt < 2; mt++) {
            const size_t r0 = (size_t)bm + wm * 32 + mt * 16 + gid;
            const size_t r1 = r0 + 8;
#pragma unroll
            for (int nt = 0; nt < 8; nt++) {
                const int col = bn + wn * 64 + nt * 8 + tg * 2;
                float2 v0 = make_float2(acc[mt][nt][0], acc[mt][nt][1]);
                float2 v1 = make_float2(acc[mt][nt][2], acc[mt][nt][3]);
                if (a.bias) {
                    float2 b2 = *(const float2*)(a.bias + col);
                    v0.x += b2.x; v0.y += b2.y; v1.x += b2.x; v1.y += b2.y;
                }
                if (a.Cin) {
                    float2 c0 = *(const float2*)(a.Cin + r0 * a.ldc + col);
                    float2 c1 = *(const float2*)(a.Cin + r1 * a.ldc + col);
                    v0.x += c0.x; v0.y += c0.y; v1.x += c1.x; v1.y += c1.y;
                }
                if (a.trunc_out) {
                    v0.x = tff(v0.x); v0.y = tff(v0.y);
                    v1.x = tff(v1.x); v1.y = tff(v1.y);
                }
                *(float2*)(a.C + r0 * a.ldc + col) = v0;
                *(float2*)(a.C + r1 * a.ldc + col) = v1;
            }
        }
    } else {
        // fused LSTM epilogue: gates (permuted 4j+t) -> smem -> pointwise
        float* gsm = sm;
#pragma unroll
        for (int mt = 0; mt < 2; mt++) {
            const int lr0 = wm * 32 + mt * 16 + gid;
            const int lr1 = lr0 + 8;
#pragma unroll
            for (int nt = 0; nt < 8; nt++) {
                const int lc = wn * 64 + nt * 8 + tg * 2;
                float2 v0 = make_float2(acc[mt][nt][0], acc[mt][nt][1]);
                float2 v1 = make_float2(acc[mt][nt][2], acc[mt][nt][3]);
                if (a.bias) {
                    float2 b2 = *(const float2*)(a.bias + bn + lc);
                    v0.x += b2.x; v0.y += b2.y; v1.x += b2.x; v1.y += b2.y;
                }
                if (a.Cin) {
                    float2 c0 = *(const float2*)(a.Cin + (size_t)(bm + lr0) * a.ldc + bn + lc);
                    float2 c1 = *(const float2*)(a.Cin + (size_t)(bm + lr1) * a.ldc + bn + lc);
                    v0.x += c0.x; v0.y += c0.y; v1.x += c1.x; v1.y += c1.y;
                }
                *(float2*)&gsm[lr0 * 132 + lc] = v0;
                *(float2*)&gsm[lr1 * 132 + lc] = v1;
            }
        }
        __syncthreads();
        const int jb = bn >> 2;
#pragma unroll
        for (int it = 0; it < 16; it++) {
            int idx = tid + it * 256;
            int row = idx >> 5, u = idx & 31;
            float4 gt = *(float4*)&gsm[row * 132 + 4 * u];
            float ii = sigf(gt.x), ff = sigf(gt.y);
            float gg = tanh_fast(gt.z), oo = sigf(gt.w);
            size_t e = (size_t)(bm + row) * HH + jb + u;
            float c_new = ff * a.c_in[e] + ii * gg;
            float h_new = oo * tanh_fast(c_new);
            a.c_out[e] = c_new;
            if (a.h_full) a.h_full[e] = h_new;
            if (a.h_tf)   a.h_tf[e] = tff(h_new);
        }
    }
}

static void launch_g(const GArgs& a, int M, int N) {
    static int attr_set = 0;
    if (!attr_set) {
        cudaFuncSetAttribute(mma_gemm_kernel,
                             cudaFuncAttributeMaxDynamicSharedMemorySize, SMEM_DYN);
        attr_set = 1;
    }
    dim3 grid(N / 128, M / 128);
    mma_gemm_kernel<<<grid, 256, SMEM_DYN>>>(a);
}

// ------------------------------ prep kernels --------------------------------
__device__ __forceinline__ int porig(int p) { return ((p & 3) << 9) | (p >> 2); }

#define PR0 ((size_t)1114112)            // wihp  2048*544
#define PR1 (PR0 + 1048576)              // whhp  2048*512
#define PR2 (PR1 + 1572864)              // wihop 2048*768
#define PR3 (PR2 + 1048576)              // whhop 2048*512
#define PR4 (PR3 + 524288)               // xtf
#define PR5 (PR4 + 1048576)              // hltf
#define PR6 (PR5 + 131072)               // wqtf
#define PR7 (PR6 + 131072)               // wkT
#define PR8 (PR7 + 65536)                // wvtf
#define PR9 (PR8 + 2048)                 // g_bias
#define PRA (PR9 + 2048)                 // g_biaso

__global__ void prep_kernel(const float* __restrict__ Wih, const float* __restrict__ Whh,
                            const float* __restrict__ bih, const float* __restrict__ bhh,
                            const float* __restrict__ Wiho, const float* __restrict__ Whho,
                            const float* __restrict__ biho,
                            const float* __restrict__ x, const float* __restrict__ hl,
                            const float* __restrict__ Wq, const float* __restrict__ Wk,
                            const float* __restrict__ Wv) {
    size_t e = (size_t)blockIdx.x * blockDim.x + threadIdx.x;
    if (e < PR0) {
        int p = (int)(e / FEATP), k = (int)(e % FEATP);
        g_wihp[e] = (k < FEAT) ? tff(Wih[(size_t)porig(p) * FEAT + k]) : 0.0f;
    } else if (e < PR1) {
        size_t i = e - PR0; int p = (int)(i >> 9), k = (int)(i & 511);
        g_whhp[i] = tff(Whh[(size_t)porig(p) * 512 + k]);
    } else if (e < PR2) {
        size_t i = e - PR1; int p = (int)(i / 768), k = (int)(i % 768);
        g_wihop[i] = tff(Wiho[(size_t)porig(p) * 768 + k]);
    } else if (e < PR3) {
        size_t i = e - PR2; int p = (int)(i >> 9), k = (int)(i & 511);
        g_whhop[i] = tff(Whho[(size_t)porig(p) * 512 + k]);
    } else if (e < PR4) {
        size_t i = e - PR3; g_xtf[i] = tff(x[i]);
    } else if (e < PR5) {
        size_t i = e - PR4; g_hltf[i] = tff(hl[i]);
    } else if (e < PR6) {
        size_t i = e - PR5; g_wqtf[i] = tff(Wq[i]);
    } else if (e < PR7) {
        size_t i = e - PR6; int d = (int)(i >> 9), h = (int)(i & 511);
        g_wkT[i] = tff(Wk[h * 256 + d]);
    } else if (e < PR8) {
        size_t i = e - PR7; g_wvtf[i] = tff(Wv[i]);
    } else if (e < PR9) {
        int p = (int)(e - PR8); int o = porig(p);
        g_bias[p] = bih[o] + bhh[o];
    } else if (e < PRA) {
        int p = (int)(e - PR9);
        g_biaso[p] = biho[porig(p)];
    }
}

__global__ void zero_hc_kernel() {
    int e = blockIdx.x * blockDim.x + threadIdx.x;
    if (e < BB * HH) { g_htf0[e] = 0.0f; g_c[e] = 0.0f; }
}

__global__ void detect_filled_kernel(const unsigned int* __restrict__ w) {
    __shared__ int flags[3];
    if (threadIdx.x < 3) flags[threadIdx.x] = 0;
    __syncthreads();
    for (int i = threadIdx.x; i < (BB * NSLOT) / 4; i += blockDim.x) {
        unsigned v = w[i];
        if (v == 0x3F800000u)      atomicOr(&flags[0], 1);
        else if (v == 0x3F803F80u) atomicOr(&flags[1], 1);
        else if (v > 1u)           atomicOr(&flags[2], 1);
    }
    __syncthreads();
    if (threadIdx.x == 0) {
        int m;
        if (flags[1])      m = 3;
        else if (flags[0]) m = 0;
        else if (flags[2]) m = 2;
        else               m = 1;
        g_fmode = m;
    }
}

__global__ void select_idx_kernel(const float* __restrict__ slots,
                                  const void* __restrict__ filled) {
    const int b = blockIdx.x;
    const int t = threadIdx.x;
    __shared__ float kq_s[DD];
    __shared__ float sims[NSLOT];
    __shared__ int   emp[NSLOT];
    for (int d = t; d < DD; d += NSLOT) kq_s[d] = g_kq[b * DD + d];
    __syncthreads();
    const float* sp = slots + ((size_t)b * NSLOT + t) * DD;
    float s = 0.0f;
    for (int d = 0; d < DD; d++) s = fmaf(sp[d], kq_s[d], s);
    sims[t] = s;
    emp[t]  = !read_filled(filled, (size_t)b * NSLOT + t, g_fmode);
    __syncthreads();
    if (t == 0) {
        int idx = -1;
        for (int n = 0; n < NSLOT; n++) if (emp[n]) { idx = n; break; }
        if (idx < 0) {
            float best = sims[0]; idx = 0;
            for (int n = 1; n < NSLOT; n++) if (sims[n] > best) { best = sims[n]; idx = n; }
        }
        g_idx[b] = idx;
    }
}

__global__ void update_write_kernel(const float* __restrict__ slots,
                                    const float* __restrict__ cum,
                                    const float* __restrict__ delta,
                                    const void* __restrict__ filled,
                                    const float* __restrict__ x,
                                    float* __restrict__ out) {
    size_t e = (size_t)blockIdx.x * blockDim.x + threadIdx.x;
    if (e >= (size_t)BB * NSLOT * DD) return;
    int d = (int)(e % DD);
    size_t bn = e / DD;
    int n = (int)(bn % NSLOT);
    int b = (int)(bn / NSLOT);
    int idx = g_idx[b];

    float xv = x[b * DD + d];
    float sl = slots[e];
    float cf = cum[e] + xv;
    if (n == idx) { sl = g_v[b * DD + d]; cf = xv; }

    out[OFF_SLOTS + e] = sl;
    out[OFF_CUM + e]   = cf;

    size_t mbase = ((size_t)n * BB + b) * FEATP;
    g_mem[mbase + d]      = tff(sl);
    g_mem[mbase + DD + d] = tff(cf);
    if (d < FEATP - FEAT) g_mem[mbase + FEAT + d] = 0.0f;
    if (d == 0) {
        float dt = (n == idx) ? 0.0f : delta[bn] + 1.0f;
        out[OFF_DELTA + bn] = dt;
        g_mem[mbase + 2 * DD] = tff(dt);
        int fl = (n == idx) ? 1 : read_filled(filled, bn, g_fmode);
        out[OFF_FILLED + bn] = fl ? 1.0f : 0.0f;
    }
}

// --------------------------------- launch -----------------------------------
extern "C" void kernel_launch(void* const* d_in, const int* in_sizes, int n_in,
                              void* d_out, int out_size) {
    const float* x_t      = (const float*)d_in[0];
    const float* h_lstm   = (const float*)d_in[1];
    const float* c_lstm   = (const float*)d_in[2];
    const float* slots    = (const float*)d_in[4];
    const float* cum      = (const float*)d_in[5];
    const float* delta    = (const float*)d_in[6];
    const void*  filled   = (const void*)d_in[7];
    const float* Wq       = (const float*)d_in[8];
    const float* Wk       = (const float*)d_in[9];
    const float* Wv       = (const float*)d_in[10];
    const float* bv       = (const float*)d_in[11];
    const float* lstm_Wih = (const float*)d_in[12];
    const float* lstm_Whh = (const float*)d_in[13];
    const float* lstm_bih = (const float*)d_in[14];
    const float* lstm_bhh = (const float*)d_in[15];
    const float* W_ih     = (const float*)d_in[16];
    const float* b_ih     = (const float*)d_in[17];
    const float* W_hh     = (const float*)d_in[18];
    float* out = (float*)d_out;

    float *p_q, *p_kq, *p_v, *p_mem, *p_xg, *p_c, *p_bias, *p_biaso;
    float *p_wihp, *p_whhp, *p_wihop, *p_whhop, *p_xtf, *p_hltf, *p_wqtf, *p_wkT, *p_wvtf;
    float *p_h0, *p_h1;
    cudaGetSymbolAddress((void**)&p_q, g_q);
    cudaGetSymbolAddress((void**)&p_kq, g_kq);
    cudaGetSymbolAddress((void**)&p_v, g_v);
    cudaGetSymbolAddress((void**)&p_mem, g_mem);
    cudaGetSymbolAddress((void**)&p_xg, g_xg);
    cudaGetSymbolAddress((void**)&p_c, g_c);
    cudaGetSymbolAddress((void**)&p_bias, g_bias);
    cudaGetSymbolAddress((void**)&p_biaso, g_biaso);
    cudaGetSymbolAddress((void**)&p_wihp, g_wihp);
    cudaGetSymbolAddress((void**)&p_whhp, g_whhp);
    cudaGetSymbolAddress((void**)&p_wihop, g_wihop);
    cudaGetSymbolAddress((void**)&p_whhop, g_whhop);
    cudaGetSymbolAddress((void**)&p_xtf, g_xtf);
    cudaGetSymbolAddress((void**)&p_hltf, g_hltf);
    cudaGetSymbolAddress((void**)&p_wqtf, g_wqtf);
    cudaGetSymbolAddress((void**)&p_wkT, g_wkT);
    cudaGetSymbolAddress((void**)&p_wvtf, g_wvtf);
    cudaGetSymbolAddress((void**)&p_h0, g_htf0);
    cudaGetSymbolAddress((void**)&p_h1, g_htf1);

    detect_filled_kernel<<<1, 256>>>((const unsigned int*)filled);
    zero_hc_kernel<<<(BB * HH + 255) / 256, 256>>>();
    prep_kernel<<<(unsigned)((PRA + 255) / 256), 256>>>(
        lstm_Wih, lstm_Whh, lstm_bih, lstm_bhh,
        W_ih, W_hh, b_ih, x_t, h_lstm, Wq, Wk, Wv);

    GArgs a;
    // q = x @ Wq.T  (trunc store, feeds kq)
    a = {}; a.mode = 0; a.K = 256; a.lda = 256; a.ldw = 256; a.ldc = 512;
    a.trunc_out = 1; a.A = p_xtf; a.W = p_wqtf; a.C = p_q;
    launch_g(a, BB, HH);
    // kq = q @ Wk   (WkT pre-transposed)
    a = {}; a.mode = 0; a.K = 512; a.lda = 512; a.ldw = 512; a.ldc = 256;
    a.A = p_q; a.W = p_wkT; a.C = p_kq;
    launch_g(a, BB, DD);
    // v = x @ Wv.T + bv
    a = {}; a.mode = 0; a.K = 256; a.lda = 256; a.ldw = 256; a.ldc = 256;
    a.A = p_xtf; a.W = p_wvtf; a.bias = bv; a.C = p_v;
    launch_g(a, BB, DD);

    select_idx_kernel<<<BB, NSLOT>>>(slots, filled);
    {
        size_t tot = (size_t)BB * NSLOT * DD;
        update_write_kernel<<<(unsigned)((tot + 255) / 256), 256>>>(
            slots, cum, delta, filled, x_t, out);
    }

    // xg = mem_seq @ WihP.T + biasP   (permuted gate layout)
    a = {}; a.mode = 0; a.K = FEATP; a.lda = FEATP; a.ldw = FEATP; a.ldc = G4;
    a.A = p_mem; a.W = p_wihp; a.bias = p_bias; a.C = p_xg;
    launch_g(a, NSLOT * BB, G4);

    // slot-LSTM recurrence with fused pointwise; h ping-pong
    for (int n = 0; n < NSLOT; n++) {
        a = {}; a.mode = 1; a.K = HH; a.lda = HH; a.ldw = HH; a.ldc = G4;
        a.A = (n & 1) ? p_h1 : p_h0;
        a.W = p_whhp;
        a.Cin = p_xg + (size_t)n * BB * G4;
        a.c_in = p_c; a.c_out = p_c;
        a.h_tf = (n & 1) ? p_h0 : p_h1;
        a.h_full = (n == NSLOT - 1) ? (out + OFF_HMEM) : nullptr;
        launch_g(a, BB, G4);
    }

    // outer LSTM: segmented K = [x(256) | h_mem(512) | h_lstm(512)], fused epilogue
    a = {}; a.mode = 2; a.K = 1280; a.ldc = G4;
    a.A = p_xtf; a.A2 = p_h0; a.A3 = p_hltf;     // final h in buf0 (n=63 writes h0)
    a.W = p_wihop; a.W2 = p_whhop; a.bias = p_biaso;
    a.c_in = c_lstm; a.c_out = out + OFF_C; a.h_full = out + OFF_H;
    launch_g(a, BB, G4);
}